// round 7
// baseline (speedup 1.0000x reference)
#include <cuda_runtime.h>
#include <cooperative_groups.h>

namespace cg = cooperative_groups;

// Problem dims
#define BB 64
#define TT 512
#define II 512
#define HH 512
#define HPAD 516            // padded H row (16B-aligned stride, conflict-free float4 LDS)
#define HBUF (8 * HPAD)     // one h buffer: 8 batches x HPAD floats

// y = (B,T,2H) floats
#define Y_ELEMS (64ull * 512ull * 1024ull)   // 33554432

// Scratch: xproj[dir][b*T+t][h], fp32. 2*32768*512 floats = 134 MB.
__device__ float g_xproj[2u * 32768u * 512u];

#define FMA2(acc, a, b) \
    asm("fma.rn.f32x2 %0, %1, %2, %0;" : "+l"(acc) : "l"(a), "l"(b))

// ---------------------------------------------------------------------------
// Kernel 1: xproj = x @ Wx^T + bias  (both directions via blockIdx.z)
//   A = x  (32768 x 512), row-major, K contiguous
//   B = Wx (512 x 512),   row-major, K contiguous  -> C = A * B^T
// 128x128 CTA tile, 16-deep K tiles, 8x8 microtile with packed f32x2 FMA.
// ---------------------------------------------------------------------------
__global__ __launch_bounds__(256) void xproj_gemm(
    const float* __restrict__ x,
    const float* __restrict__ Wf, const float* __restrict__ bf,
    const float* __restrict__ Wb, const float* __restrict__ bb)
{
    __shared__ float As[16][132];   // [k][m], padded
    __shared__ float Bs[16][136];   // [k][n], padded

    const int dir = blockIdx.z;
    const float* __restrict__ W    = dir ? Wb : Wf;
    const float* __restrict__ bias = dir ? bb : bf;
    float* __restrict__ outp = g_xproj + (size_t)dir * (32768ull * 512ull);

    const int rm = blockIdx.y * 128;   // m tile (rows of x)
    const int cn = blockIdx.x * 128;   // n tile (rows of W = output h)
    const int t  = threadIdx.x;
    const int tx = t & 15, ty = t >> 4;
    const int m0 = ty * 8, n0 = tx * 8;

    unsigned long long acc[8][4];   // 8 rows x 4 packed n-pairs
#pragma unroll
    for (int i = 0; i < 8; ++i)
#pragma unroll
        for (int p = 0; p < 4; ++p) acc[i][p] = 0ull;

    for (int k0 = 0; k0 < 512; k0 += 16) {
#pragma unroll
        for (int i = 0; i < 2; ++i) {
            int f   = t + 256 * i;          // 0..511 float4 slots
            int row = f >> 2;               // 0..127
            int kc  = (f & 3) << 2;         // 0,4,8,12
            float4 va = *(const float4*)(x + (size_t)(rm + row) * 512 + k0 + kc);
            As[kc + 0][row] = va.x; As[kc + 1][row] = va.y;
            As[kc + 2][row] = va.z; As[kc + 3][row] = va.w;
            float4 vb = *(const float4*)(W + (size_t)(cn + row) * 512 + k0 + kc);
            Bs[kc + 0][row] = vb.x; Bs[kc + 1][row] = vb.y;
            Bs[kc + 2][row] = vb.z; Bs[kc + 3][row] = vb.w;
        }
        __syncthreads();

#pragma unroll
        for (int k = 0; k < 16; ++k) {
            float4 a0 = *(const float4*)&As[k][m0];
            float4 a1 = *(const float4*)&As[k][m0 + 4];
            ulonglong2 q0 = *(const ulonglong2*)&Bs[k][n0];      // pairs n0..n0+3
            ulonglong2 q1 = *(const ulonglong2*)&Bs[k][n0 + 4];  // pairs n0+4..n0+7
            float ar[8] = {a0.x, a0.y, a0.z, a0.w, a1.x, a1.y, a1.z, a1.w};
#pragma unroll
            for (int i = 0; i < 8; ++i) {
                unsigned long long s;
                asm("mov.b64 %0, {%1, %1};" : "=l"(s) : "f"(ar[i]));
                FMA2(acc[i][0], s, q0.x);
                FMA2(acc[i][1], s, q0.y);
                FMA2(acc[i][2], s, q1.x);
                FMA2(acc[i][3], s, q1.y);
            }
        }
        __syncthreads();
    }

    // Epilogue: unpack, add bias, store
#pragma unroll
    for (int i = 0; i < 8; ++i) {
        size_t row = (size_t)(rm + m0 + i);
#pragma unroll
        for (int p = 0; p < 4; ++p) {
            float lo, hi;
            asm("mov.b64 {%0, %1}, %2;" : "=f"(lo), "=f"(hi) : "l"(acc[i][p]));
            int c = cn + n0 + p * 2;
            float2 o;
            o.x = lo + bias[c];
            o.y = hi + bias[c + 1];
            *(float2*)(outp + row * 512 + c) = o;
        }
    }
}

// ---------------------------------------------------------------------------
// Kernel 2: recurrence. 16 clusters of 8 CTAs (8 fwd + 8 bwd clusters).
// Each cluster owns 8 batch rows of one direction; cluster CTA `rank` owns
// Wh rows [rank*64, rank*64+64) resident in SMEM. Per step:
//   - each lane computes 2 outputs (b fixed, j pair): 512-long dots from SMEM
//     using packed f32x2 FMA (k-parity lanes, horizontal add at the end)
//   - tanh(xproj + dot), write y, push h slice (at GLOBAL j offset!) to all
//     8 peers' next buffer via DSMEM stores
//   - cluster.sync, swap double-buffered h
// ---------------------------------------------------------------------------
#define REC_SMEM_BYTES ((64 * HPAD + 2 * 8 * HPAD) * 4)   // 165120 B

__global__ __launch_bounds__(256, 1) __cluster_dims__(8, 1, 1)
void rnn_rec(const float* __restrict__ h0f, const float* __restrict__ h0b,
             const float* __restrict__ Whf, const float* __restrict__ Whb,
             float* __restrict__ out)
{
    extern __shared__ float smf[];
    float* Wh = smf;                 // [64][HPAD]  this CTA's Wh rows
    float* hb = smf + 64 * HPAD;     // two h buffers, each [8][HPAD]

    cg::cluster_group cluster = cg::this_cluster();
    const int rank = (int)cluster.block_rank();
    const int cid  = blockIdx.x >> 3;     // 0..15
    const int dir  = cid >> 3;            // 0 fwd, 1 bwd
    const int b0   = (cid & 7) * 8;       // batch group base
    const int tid  = threadIdx.x;

    // Load this CTA's 64 rows of Wh (row-major [jl][k])
    const float* __restrict__ Whg = dir ? Whb : Whf;
    for (int i = tid; i < 64 * 128; i += 256) {
        int jl = i >> 7;
        int kc = (i & 127) << 2;
        float4 v = *(const float4*)(Whg + (size_t)(rank * 64 + jl) * 512 + kc);
        float* d = Wh + jl * HPAD + kc;
        d[0] = v.x; d[1] = v.y; d[2] = v.z; d[3] = v.w;
    }
    // Init h buffer 0 from h0 (full 512 per batch row)
    const float* __restrict__ h0 = dir ? h0b : h0f;
    for (int i = tid; i < 8 * 128; i += 256) {
        int bb = i >> 7;
        int kc = (i & 127) << 2;
        float4 v = *(const float4*)(h0 + (size_t)(b0 + bb) * 512 + kc);
        float* d = hb + bb * HPAD + kc;
        d[0] = v.x; d[1] = v.y; d[2] = v.z; d[3] = v.w;
    }
    __syncthreads();

    // Peer base pointers (both buffers at fixed offsets from hb in every CTA)
    float* peer[8];
#pragma unroll
    for (int r = 0; r < 8; ++r)
        peer[r] = (float*)cluster.map_shared_rank((void*)hb, r);

    cluster.sync();

    // Work assignment: warp w -> local j block [w*8, w*8+8); lane: b = l>>2,
    // j pair = w*8 + (l&3)*2. Covers 8 batches x 64 j exactly once.
    const int w  = tid >> 5, l = tid & 31;
    const int b  = l >> 2;
    const int jl = w * 8 + (l & 3) * 2;
    const int jg = rank * 64 + jl;          // GLOBAL j index

    const float* __restrict__ Wr0 = Wh + jl * HPAD;
    const float* __restrict__ Wr1 = Wh + (jl + 1) * HPAD;
    const float* __restrict__ xpb =
        g_xproj + (size_t)dir * (32768ull * 512ull) + (size_t)(b0 + b) * 512ull * 512ull + jg;
    float* __restrict__ yb = out + (size_t)(b0 + b) * 512ull * 1024ull + dir * 512 + jg;

    int co = 0;   // current buffer offset (0 or HBUF)
    for (int s = 0; s < 512; ++s) {
        const int tt = dir ? (511 - s) : s;
        // prefetch xproj for this step (consumed after the dot product)
        float2 xp = *(const float2*)(xpb + (size_t)tt * 512);

        const float* __restrict__ hv = hb + co + b * HPAD;
        // 4 packed accumulators: p* for output jg, q* for output jg+1,
        // packed over k parity (lo = even k, hi = odd k).
        unsigned long long p0 = 0ull, p1 = 0ull, q0 = 0ull, q1 = 0ull;
#pragma unroll 4
        for (int k = 0; k < 512; k += 8) {
            ulonglong2 hA = *(const ulonglong2*)(hv + k);       // k..k+3 (2 pairs)
            ulonglong2 hB = *(const ulonglong2*)(hv + k + 4);   // k+4..k+7
            ulonglong2 wa = *(const ulonglong2*)(Wr0 + k);
            ulonglong2 wb = *(const ulonglong2*)(Wr0 + k + 4);
            ulonglong2 wc = *(const ulonglong2*)(Wr1 + k);
            ulonglong2 wd = *(const ulonglong2*)(Wr1 + k + 4);
            FMA2(p0, hA.x, wa.x); FMA2(p1, hA.y, wa.y);
            FMA2(q0, hA.x, wc.x); FMA2(q1, hA.y, wc.y);
            FMA2(p0, hB.x, wb.x); FMA2(p1, hB.y, wb.y);
            FMA2(q0, hB.x, wd.x); FMA2(q1, hB.y, wd.y);
        }
        float p0l, p0h, p1l, p1h, q0l, q0h, q1l, q1h;
        asm("mov.b64 {%0, %1}, %2;" : "=f"(p0l), "=f"(p0h) : "l"(p0));
        asm("mov.b64 {%0, %1}, %2;" : "=f"(p1l), "=f"(p1h) : "l"(p1));
        asm("mov.b64 {%0, %1}, %2;" : "=f"(q0l), "=f"(q0h) : "l"(q0));
        asm("mov.b64 {%0, %1}, %2;" : "=f"(q1l), "=f"(q1h) : "l"(q1));
        float v0 = tanhf(xp.x + ((p0l + p0h) + (p1l + p1h)));
        float v1 = tanhf(xp.y + ((q0l + q0h) + (q1l + q1h)));
        float2 hnew = make_float2(v0, v1);

        // write y[b][tt][dir*512 + jg .. +1]
        *(float2*)(yb + (size_t)tt * 1024) = hnew;

        // push to the NEXT buffer of all 8 cluster CTAs (incl. self),
        // at the GLOBAL j offset.
        const int wo  = co ^ HBUF;
        const int off = wo + b * HPAD + jg;
#pragma unroll
        for (int r = 0; r < 8; ++r)
            *(float2*)(peer[r] + off) = hnew;

        cluster.sync();     // release our stores / acquire peers' stores
        co = wo;
    }

    // Final hidden states: hT_f then hT_b after y
    float* __restrict__ hT = out + Y_ELEMS + (size_t)dir * (64ull * 512ull) + (size_t)b0 * 512ull;
    const float* __restrict__ hfin = hb + co;
    for (int i = tid; i < 8 * 512; i += 256) {
        int bb = i >> 9;
        int k  = i & 511;
        hT[bb * 512 + k] = hfin[bb * HPAD + k];
    }
}

// ---------------------------------------------------------------------------
// Launch
// ---------------------------------------------------------------------------
extern "C" void kernel_launch(void* const* d_in, const int* in_sizes, int n_in,
                              void* d_out, int out_size)
{
    const float* x    = (const float*)d_in[0];
    const float* h0f  = (const float*)d_in[1];
    const float* h0b  = (const float*)d_in[2];
    const float* Wxfw = (const float*)d_in[3];
    const float* Wxfb = (const float*)d_in[4];
    const float* Whfw = (const float*)d_in[5];
    const float* Wxbw = (const float*)d_in[6];
    const float* Wxbb = (const float*)d_in[7];
    const float* Whbw = (const float*)d_in[8];
    float* out = (float*)d_out;

    // Phase 1: input projections for both directions
    dim3 g1(4, 256, 2);   // n-tiles, m-tiles, dir
    xproj_gemm<<<g1, 256>>>(x, Wxfw, Wxfb, Wxbw, Wxbb);

    // Phase 2: persistent clustered recurrence (both directions concurrently)
    cudaFuncSetAttribute(rnn_rec, cudaFuncAttributeMaxDynamicSharedMemorySize,
                         REC_SMEM_BYTES);
    rnn_rec<<<128, 256, REC_SMEM_BYTES>>>(h0f, h0b, Whfw, Whbw, out);
}

// round 11
// speedup vs baseline: 1.5320x; 1.5320x over previous
#include <cuda_runtime.h>
#include <cooperative_groups.h>

namespace cg = cooperative_groups;

// Problem dims
#define HPAD 516            // padded h row stride (floats): conflict-free + 16B aligned
#define HBUF (8 * HPAD)     // one h buffer: 8 batches x HPAD floats

#define Y_ELEMS (64ull * 512ull * 1024ull)   // y = (B,T,2H)

// Scratch: xproj[dir][b*T+t][h], fp32. 134 MB.
__device__ float g_xproj[2u * 32768u * 512u];

#define FMA2(acc, a, b) \
    asm("fma.rn.f32x2 %0, %1, %2, %0;" : "+l"(acc) : "l"(a), "l"(b))

// ---------------------------------------------------------------------------
// Kernel 1: xproj = x @ Wx^T + bias  (both directions via blockIdx.z)
// (unchanged from passing R6 kernel)
// ---------------------------------------------------------------------------
__global__ __launch_bounds__(256) void xproj_gemm(
    const float* __restrict__ x,
    const float* __restrict__ Wf, const float* __restrict__ bf,
    const float* __restrict__ Wb, const float* __restrict__ bb)
{
    __shared__ float As[16][132];   // [k][m], padded
    __shared__ float Bs[16][136];   // [k][n], padded

    const int dir = blockIdx.z;
    const float* __restrict__ W    = dir ? Wb : Wf;
    const float* __restrict__ bias = dir ? bb : bf;
    float* __restrict__ outp = g_xproj + (size_t)dir * (32768ull * 512ull);

    const int rm = blockIdx.y * 128;
    const int cn = blockIdx.x * 128;
    const int t  = threadIdx.x;
    const int tx = t & 15, ty = t >> 4;
    const int m0 = ty * 8, n0 = tx * 8;

    unsigned long long acc[8][4];
#pragma unroll
    for (int i = 0; i < 8; ++i)
#pragma unroll
        for (int p = 0; p < 4; ++p) acc[i][p] = 0ull;

    for (int k0 = 0; k0 < 512; k0 += 16) {
#pragma unroll
        for (int i = 0; i < 2; ++i) {
            int f   = t + 256 * i;
            int row = f >> 2;
            int kc  = (f & 3) << 2;
            float4 va = *(const float4*)(x + (size_t)(rm + row) * 512 + k0 + kc);
            As[kc + 0][row] = va.x; As[kc + 1][row] = va.y;
            As[kc + 2][row] = va.z; As[kc + 3][row] = va.w;
            float4 vb = *(const float4*)(W + (size_t)(cn + row) * 512 + k0 + kc);
            Bs[kc + 0][row] = vb.x; Bs[kc + 1][row] = vb.y;
            Bs[kc + 2][row] = vb.z; Bs[kc + 3][row] = vb.w;
        }
        __syncthreads();

#pragma unroll
        for (int k = 0; k < 16; ++k) {
            float4 a0 = *(const float4*)&As[k][m0];
            float4 a1 = *(const float4*)&As[k][m0 + 4];
            ulonglong2 q0 = *(const ulonglong2*)&Bs[k][n0];
            ulonglong2 q1 = *(const ulonglong2*)&Bs[k][n0 + 4];
            float ar[8] = {a0.x, a0.y, a0.z, a0.w, a1.x, a1.y, a1.z, a1.w};
#pragma unroll
            for (int i = 0; i < 8; ++i) {
                unsigned long long s;
                asm("mov.b64 %0, {%1, %1};" : "=l"(s) : "f"(ar[i]));
                FMA2(acc[i][0], s, q0.x);
                FMA2(acc[i][1], s, q0.y);
                FMA2(acc[i][2], s, q1.x);
                FMA2(acc[i][3], s, q1.y);
            }
        }
        __syncthreads();
    }

#pragma unroll
    for (int i = 0; i < 8; ++i) {
        size_t row = (size_t)(rm + m0 + i);
#pragma unroll
        for (int p = 0; p < 4; ++p) {
            float lo, hi;
            asm("mov.b64 {%0, %1}, %2;" : "=f"(lo), "=f"(hi) : "l"(acc[i][p]));
            int c = cn + n0 + p * 2;
            float2 o;
            o.x = lo + bias[c];
            o.y = hi + bias[c + 1];
            *(float2*)(outp + row * 512 + c) = o;
        }
    }
}

// ---------------------------------------------------------------------------
// Kernel 2: recurrence with REGISTER-RESIDENT Wh.
// 16 clusters of 8 CTAs (8 fwd + 8 bwd). CTA `rank` owns Wh rows
// [rank*64, rank*64+64). Lane (w,l): jblk = w*4+(l>>3) in 0..31, kg = l&7.
// Lane permanently holds W[2 rows jg,jg+1][k = m*32+kg*4 .. +3, m=0..15]
// in 128 registers. Per step:
//   - for all 8 batches: partial dots against SMEM h (broadcast LDS,
//     conflict-free 128B wavefronts), accumulated in packed f32x2 regs
//   - 3-level shfl reduce-scatter over the 8 kg lanes -> lane ends with
//     the full dot for batch b == kg, j-pair (jg, jg+1)
//   - tanh(xproj + dot), store y, push float2 to all 8 peers' next h buffer
//   - cluster.sync, swap buffers
// ---------------------------------------------------------------------------
__global__ __launch_bounds__(256, 1) __cluster_dims__(8, 1, 1)
void rnn_rec(const float* __restrict__ h0f, const float* __restrict__ h0b,
             const float* __restrict__ Whf, const float* __restrict__ Whb,
             float* __restrict__ out)
{
    __shared__ float hb[2 * HBUF];   // double-buffered h: [2][8 b][HPAD]

    cg::cluster_group cluster = cg::this_cluster();
    const int rank = (int)cluster.block_rank();
    const int cid  = blockIdx.x >> 3;     // 0..15
    const int dir  = cid >> 3;            // 0 fwd, 1 bwd
    const int b0   = (cid & 7) * 8;       // batch group base
    const int tid  = threadIdx.x;
    const int w    = tid >> 5, l = tid & 31;
    const int jblk = w * 4 + (l >> 3);    // 0..31
    const int kg   = l & 7;               // k-group AND final batch index
    const int jg   = rank * 64 + 2 * jblk;   // global j of this lane's pair

    // ---- init h buffer 0 from h0 ----
    const float* __restrict__ h0 = dir ? h0b : h0f;
    for (int i = tid; i < 8 * 128; i += 256) {
        int bb = i >> 7;
        int kc = (i & 127) << 2;
        float4 v = *(const float4*)(h0 + (size_t)(b0 + bb) * 512 + kc);
        float* d = hb + bb * HPAD + kc;
        d[0] = v.x; d[1] = v.y; d[2] = v.z; d[3] = v.w;
    }

    // ---- load this lane's Wh slice into registers ----
    // Row jg:   wA[m] = W[jg][m*32 + kg*4 .. +3]   (two packed f32x2)
    // Row jg+1: wB[m]
    const float* __restrict__ Whg = dir ? Whb : Whf;
    ulonglong2 wA[16], wB[16];
    {
        const float* r0 = Whg + (size_t)jg * 512 + kg * 4;
        const float* r1 = r0 + 512;
#pragma unroll
        for (int m = 0; m < 16; ++m) {
            wA[m] = *(const ulonglong2*)(r0 + m * 32);
            wB[m] = *(const ulonglong2*)(r1 + m * 32);
        }
    }
    __syncthreads();

    float* peer[8];
#pragma unroll
    for (int r = 0; r < 8; ++r)
        peer[r] = (float*)cluster.map_shared_rank((void*)hb, r);

    cluster.sync();

    // Fixed per-lane pointers: batch = b0 + kg, columns jg..jg+1
    const float* __restrict__ xpb =
        g_xproj + (size_t)dir * (32768ull * 512ull)
                + (size_t)(b0 + kg) * (512ull * 512ull) + jg;
    float* __restrict__ yb =
        out + (size_t)(b0 + kg) * (512ull * 1024ull) + (size_t)dir * 512 + jg;
    const int lane_off = kg * HPAD + jg;     // push slot (b=kg, global j)

    int co = 0;   // current buffer offset (0 or HBUF)
    for (int s = 0; s < 512; ++s) {
        const int tt = dir ? (511 - s) : s;
        float2 xp = *(const float2*)(xpb + (size_t)tt * 512);

        // ---- partial dots for all 8 batches ----
        unsigned long long a0[8], a1[8];
#pragma unroll
        for (int b = 0; b < 8; ++b) { a0[b] = 0ull; a1[b] = 0ull; }
        const float* __restrict__ hv = hb + co + kg * 4;
#pragma unroll
        for (int m = 0; m < 16; ++m) {
#pragma unroll
            for (int b = 0; b < 8; ++b) {
                ulonglong2 h2 = *(const ulonglong2*)(hv + b * HPAD + m * 32);
                FMA2(a0[b], h2.x, wA[m].x);
                FMA2(a0[b], h2.y, wA[m].y);
                FMA2(a1[b], h2.x, wB[m].x);
                FMA2(a1[b], h2.y, wB[m].y);
            }
        }

        // horizontal add of packed halves -> v0[b] (j=jg), v1[b] (j=jg+1)
        float v0[8], v1[8];
#pragma unroll
        for (int b = 0; b < 8; ++b) {
            float lo, hi;
            asm("mov.b64 {%0, %1}, %2;" : "=f"(lo), "=f"(hi) : "l"(a0[b]));
            v0[b] = lo + hi;
            asm("mov.b64 {%0, %1}, %2;" : "=f"(lo), "=f"(hi) : "l"(a1[b]));
            v1[b] = lo + hi;
        }

        // ---- reduce-scatter over the 8 kg lanes: survivor batch == kg ----
        // level mask 4 (bit2)
        float u0[4], u1[4];
        {
            const bool hi = (l & 4);
#pragma unroll
            for (int i = 0; i < 4; ++i) {
                float s0 = hi ? v0[i] : v0[i + 4];
                float k0 = hi ? v0[i + 4] : v0[i];
                u0[i] = k0 + __shfl_xor_sync(0xffffffffu, s0, 4);
                float s1 = hi ? v1[i] : v1[i + 4];
                float k1 = hi ? v1[i + 4] : v1[i];
                u1[i] = k1 + __shfl_xor_sync(0xffffffffu, s1, 4);
            }
        }
        // level mask 2 (bit1)
        float t0[2], t1[2];
        {
            const bool hi = (l & 2);
#pragma unroll
            for (int i = 0; i < 2; ++i) {
                float s0 = hi ? u0[i] : u0[i + 2];
                float k0 = hi ? u0[i + 2] : u0[i];
                t0[i] = k0 + __shfl_xor_sync(0xffffffffu, s0, 2);
                float s1 = hi ? u1[i] : u1[i + 2];
                float k1 = hi ? u1[i + 2] : u1[i];
                t1[i] = k1 + __shfl_xor_sync(0xffffffffu, s1, 2);
            }
        }
        // level mask 1 (bit0)
        float f0, f1;
        {
            const bool hi = (l & 1);
            float s0 = hi ? t0[0] : t0[1];
            float k0 = hi ? t0[1] : t0[0];
            f0 = k0 + __shfl_xor_sync(0xffffffffu, s0, 1);
            float s1 = hi ? t1[0] : t1[1];
            float k1 = hi ? t1[1] : t1[0];
            f1 = k1 + __shfl_xor_sync(0xffffffffu, s1, 1);
        }

        // ---- activation + output + cluster push ----
        float r0 = tanhf(xp.x + f0);
        float r1 = tanhf(xp.y + f1);
        float2 hn = make_float2(r0, r1);

        *(float2*)(yb + (size_t)tt * 1024) = hn;   // y[b][tt][dir*512+jg..+1]

        const int wo = co ^ HBUF;
#pragma unroll
        for (int r = 0; r < 8; ++r)
            *(float2*)(peer[r] + wo + lane_off) = hn;

        cluster.sync();   // release our pushes / acquire peers' pushes
        co = wo;
    }

    // ---- final hidden states: hT_f then hT_b after y ----
    float* __restrict__ hT =
        out + Y_ELEMS + (size_t)dir * (64ull * 512ull) + (size_t)b0 * 512ull;
    const float* __restrict__ hfin = hb + co;
    for (int i = tid; i < 8 * 512; i += 256) {
        int bb = i >> 9;
        int k  = i & 511;
        hT[bb * 512 + k] = hfin[bb * HPAD + k];
    }
}

// ---------------------------------------------------------------------------
// Launch
// ---------------------------------------------------------------------------
extern "C" void kernel_launch(void* const* d_in, const int* in_sizes, int n_in,
                              void* d_out, int out_size)
{
    const float* x    = (const float*)d_in[0];
    const float* h0f  = (const float*)d_in[1];
    const float* h0b  = (const float*)d_in[2];
    const float* Wxfw = (const float*)d_in[3];
    const float* Wxfb = (const float*)d_in[4];
    const float* Whfw = (const float*)d_in[5];
    const float* Wxbw = (const float*)d_in[6];
    const float* Wxbb = (const float*)d_in[7];
    const float* Whbw = (const float*)d_in[8];
    float* out = (float*)d_out;

    // Phase 1: input projections for both directions
    dim3 g1(4, 256, 2);
    xproj_gemm<<<g1, 256>>>(x, Wxfw, Wxfb, Wxbw, Wxbb);

    // Phase 2: persistent clustered recurrence (both directions concurrently)
    rnn_rec<<<128, 256>>>(h0f, h0b, Whfw, Whbw, out);
}

// round 12
// speedup vs baseline: 1.9053x; 1.2437x over previous
#include <cuda_runtime.h>
#include <cooperative_groups.h>

namespace cg = cooperative_groups;

#define HPAD 516            // padded h row stride (floats)
#define HBUF (8 * HPAD)     // one h buffer: 8 batches x HPAD floats

#define Y_ELEMS (64ull * 512ull * 1024ull)   // y = (B,T,2H)

// Scratch: xproj[dir][b*T+t][h], fp32. 134 MB.
__device__ float g_xproj[2u * 32768u * 512u];

#define FMA2(acc, a, b) \
    asm("fma.rn.f32x2 %0, %1, %2, %0;" : "+l"(acc) : "l"(a), "l"(b))

// ---------------------------------------------------------------------------
// Kernel 1: xproj = x @ Wx^T + bias  (both directions via blockIdx.z)
// (unchanged — ~72% of fp32 peak already)
// ---------------------------------------------------------------------------
__global__ __launch_bounds__(256) void xproj_gemm(
    const float* __restrict__ x,
    const float* __restrict__ Wf, const float* __restrict__ bf,
    const float* __restrict__ Wb, const float* __restrict__ bb)
{
    __shared__ float As[16][132];
    __shared__ float Bs[16][136];

    const int dir = blockIdx.z;
    const float* __restrict__ W    = dir ? Wb : Wf;
    const float* __restrict__ bias = dir ? bb : bf;
    float* __restrict__ outp = g_xproj + (size_t)dir * (32768ull * 512ull);

    const int rm = blockIdx.y * 128;
    const int cn = blockIdx.x * 128;
    const int t  = threadIdx.x;
    const int tx = t & 15, ty = t >> 4;
    const int m0 = ty * 8, n0 = tx * 8;

    unsigned long long acc[8][4];
#pragma unroll
    for (int i = 0; i < 8; ++i)
#pragma unroll
        for (int p = 0; p < 4; ++p) acc[i][p] = 0ull;

    for (int k0 = 0; k0 < 512; k0 += 16) {
#pragma unroll
        for (int i = 0; i < 2; ++i) {
            int f   = t + 256 * i;
            int row = f >> 2;
            int kc  = (f & 3) << 2;
            float4 va = *(const float4*)(x + (size_t)(rm + row) * 512 + k0 + kc);
            As[kc + 0][row] = va.x; As[kc + 1][row] = va.y;
            As[kc + 2][row] = va.z; As[kc + 3][row] = va.w;
            float4 vb = *(const float4*)(W + (size_t)(cn + row) * 512 + k0 + kc);
            Bs[kc + 0][row] = vb.x; Bs[kc + 1][row] = vb.y;
            Bs[kc + 2][row] = vb.z; Bs[kc + 3][row] = vb.w;
        }
        __syncthreads();

#pragma unroll
        for (int k = 0; k < 16; ++k) {
            float4 a0 = *(const float4*)&As[k][m0];
            float4 a1 = *(const float4*)&As[k][m0 + 4];
            ulonglong2 q0 = *(const ulonglong2*)&Bs[k][n0];
            ulonglong2 q1 = *(const ulonglong2*)&Bs[k][n0 + 4];
            float ar[8] = {a0.x, a0.y, a0.z, a0.w, a1.x, a1.y, a1.z, a1.w};
#pragma unroll
            for (int i = 0; i < 8; ++i) {
                unsigned long long s;
                asm("mov.b64 %0, {%1, %1};" : "=l"(s) : "f"(ar[i]));
                FMA2(acc[i][0], s, q0.x);
                FMA2(acc[i][1], s, q0.y);
                FMA2(acc[i][2], s, q1.x);
                FMA2(acc[i][3], s, q1.y);
            }
        }
        __syncthreads();
    }

#pragma unroll
    for (int i = 0; i < 8; ++i) {
        size_t row = (size_t)(rm + m0 + i);
#pragma unroll
        for (int p = 0; p < 4; ++p) {
            float lo, hi;
            asm("mov.b64 {%0, %1}, %2;" : "=f"(lo), "=f"(hi) : "l"(acc[i][p]));
            int c = cn + n0 + p * 2;
            float2 o;
            o.x = lo + bias[c];
            o.y = hi + bias[c + 1];
            *(float2*)(outp + row * 512 + c) = o;
        }
    }
}

// ---------------------------------------------------------------------------
// Kernel 2: recurrence, register-resident Wh, R=4 rows/lane (LDS/FMA balanced)
// 16 clusters of 8 CTAs. CTA `rank` owns Wh rows [rank*64, rank*64+64).
// Lane: jblk = tid>>4 (rows 4*jblk..+3), kg = tid&15 (k = kg*4 + m*64).
// Per step: 64 LDS.128 (8 b x 8 m), 512 FFMA2 into 32 packed accumulators,
// 4-level shfl reduce-scatter over 16 kg-lanes -> lane ends with float2 for
// batch kg>>1, j-pair 4*jblk + 2*(kg&1). Split cluster barrier (arrive after
// pushes, wait after next step's xproj prefetch).
// ---------------------------------------------------------------------------
__global__ __launch_bounds__(256, 1) __cluster_dims__(8, 1, 1)
void rnn_rec(const float* __restrict__ h0f, const float* __restrict__ h0b,
             const float* __restrict__ Whf, const float* __restrict__ Whb,
             float* __restrict__ out)
{
    __shared__ float hb[2 * HBUF];   // double-buffered h: [2][8 b][HPAD]

    cg::cluster_group cluster = cg::this_cluster();
    const int rank = (int)cluster.block_rank();
    const int cid  = blockIdx.x >> 3;     // 0..15
    const int dir  = cid >> 3;            // 0 fwd, 1 bwd
    const int b0   = (cid & 7) * 8;       // batch group base
    const int tid  = threadIdx.x;
    const int jblk = tid >> 4;            // 0..15 -> rows 4*jblk..4*jblk+3
    const int kg   = tid & 15;            // k-group

    // ---- init h buffer 0 from h0 ----
    const float* __restrict__ h0 = dir ? h0b : h0f;
    for (int i = tid; i < 8 * 128; i += 256) {
        int bb = i >> 7;
        int kc = (i & 127) << 2;
        float4 v = *(const float4*)(h0 + (size_t)(b0 + bb) * 512 + kc);
        float* d = hb + bb * HPAD + kc;
        d[0] = v.x; d[1] = v.y; d[2] = v.z; d[3] = v.w;
    }

    // ---- load this lane's Wh slice: 4 rows x (kg*4 + m*64, m=0..7) ----
    const float* __restrict__ Whg = dir ? Whb : Whf;
    ulonglong2 wR[4][8];
    {
#pragma unroll
        for (int r = 0; r < 4; ++r) {
            const float* rp = Whg + (size_t)(rank * 64 + 4 * jblk + r) * 512 + kg * 4;
#pragma unroll
            for (int m = 0; m < 8; ++m)
                wR[r][m] = *(const ulonglong2*)(rp + m * 64);
        }
    }
    __syncthreads();

    float* peer[8];
#pragma unroll
    for (int r = 0; r < 8; ++r)
        peer[r] = (float*)cluster.map_shared_rank((void*)hb, r);

    cluster.sync();

    // Output assignment for this lane after reduce-scatter:
    const int b_out  = kg >> 1;                              // 0..7
    const int jg_out = rank * 64 + 4 * jblk + 2 * (kg & 1);  // global j (even)

    const float* __restrict__ xpb =
        g_xproj + (size_t)dir * (32768ull * 512ull)
                + (size_t)(b0 + b_out) * (512ull * 512ull) + jg_out;
    float* __restrict__ yb =
        out + (size_t)(b0 + b_out) * (512ull * 1024ull) + (size_t)dir * 512 + jg_out;
    const int lane_off = b_out * HPAD + jg_out;   // push slot

    int co = 0;   // current buffer offset (0 or HBUF)
    for (int s = 0; s < 512; ++s) {
        const int tt = dir ? (511 - s) : s;
        float2 xp = *(const float2*)(xpb + (size_t)tt * 512);

        if (s > 0)
            asm volatile("barrier.cluster.wait.aligned;" ::: "memory");

        // ---- partial dots: 8 batches x 4 rows, packed over k ----
        unsigned long long acc[8][4];
#pragma unroll
        for (int b = 0; b < 8; ++b)
#pragma unroll
            for (int r = 0; r < 4; ++r) acc[b][r] = 0ull;

        const float* __restrict__ hv = hb + co + kg * 4;
#pragma unroll
        for (int m = 0; m < 8; ++m) {
#pragma unroll
            for (int b = 0; b < 8; ++b) {
                ulonglong2 h2 = *(const ulonglong2*)(hv + b * HPAD + m * 64);
#pragma unroll
                for (int r = 0; r < 4; ++r) {
                    FMA2(acc[b][r], h2.x, wR[r][m].x);
                    FMA2(acc[b][r], h2.y, wR[r][m].y);
                }
            }
        }

        // ---- unpack halves: P[v], v = b*4 + r ----
        float P[32];
#pragma unroll
        for (int b = 0; b < 8; ++b)
#pragma unroll
            for (int r = 0; r < 4; ++r) {
                float lo, hi;
                asm("mov.b64 {%0, %1}, %2;" : "=f"(lo), "=f"(hi) : "l"(acc[b][r]));
                P[b * 4 + r] = lo + hi;
            }

        // ---- reduce-scatter over 16 kg lanes ----
        float Q[16];
        {
            const bool hi = (kg & 8);
#pragma unroll
            for (int i = 0; i < 16; ++i) {
                float keep  = hi ? P[i + 16] : P[i];
                float send  = hi ? P[i] : P[i + 16];
                Q[i] = keep + __shfl_xor_sync(0xffffffffu, send, 8);
            }
        }
        float R_[8];
        {
            const bool hi = (kg & 4);
#pragma unroll
            for (int i = 0; i < 8; ++i) {
                float keep = hi ? Q[i + 8] : Q[i];
                float send = hi ? Q[i] : Q[i + 8];
                R_[i] = keep + __shfl_xor_sync(0xffffffffu, send, 4);
            }
        }
        float S_[4];
        {
            const bool hi = (kg & 2);
#pragma unroll
            for (int i = 0; i < 4; ++i) {
                float keep = hi ? R_[i + 4] : R_[i];
                float send = hi ? R_[i] : R_[i + 4];
                S_[i] = keep + __shfl_xor_sync(0xffffffffu, send, 2);
            }
        }
        float F0, F1;
        {
            const bool hi = (kg & 1);
            float k0 = hi ? S_[2] : S_[0];
            float s0 = hi ? S_[0] : S_[2];
            F0 = k0 + __shfl_xor_sync(0xffffffffu, s0, 1);
            float k1 = hi ? S_[3] : S_[1];
            float s1 = hi ? S_[1] : S_[3];
            F1 = k1 + __shfl_xor_sync(0xffffffffu, s1, 1);
        }

        // ---- activation + output + cluster push ----
        float r0 = tanhf(xp.x + F0);
        float r1 = tanhf(xp.y + F1);
        float2 hn = make_float2(r0, r1);

        *(float2*)(yb + (size_t)tt * 1024) = hn;

        const int wo = co ^ HBUF;
#pragma unroll
        for (int r = 0; r < 8; ++r)
            *(float2*)(peer[r] + wo + lane_off) = hn;

        asm volatile("barrier.cluster.arrive.aligned;" ::: "memory");
        co = wo;
    }
    asm volatile("barrier.cluster.wait.aligned;" ::: "memory");

    // ---- final hidden states: hT_f then hT_b after y ----
    float* __restrict__ hT =
        out + Y_ELEMS + (size_t)dir * (64ull * 512ull) + (size_t)b0 * 512ull;
    const float* __restrict__ hfin = hb + co;
    for (int i = tid; i < 8 * 512; i += 256) {
        int bb = i >> 9;
        int k  = i & 511;
        hT[bb * 512 + k] = hfin[bb * HPAD + k];
    }
}

// ---------------------------------------------------------------------------
// Launch
// ---------------------------------------------------------------------------
extern "C" void kernel_launch(void* const* d_in, const int* in_sizes, int n_in,
                              void* d_out, int out_size)
{
    const float* x    = (const float*)d_in[0];
    const float* h0f  = (const float*)d_in[1];
    const float* h0b  = (const float*)d_in[2];
    const float* Wxfw = (const float*)d_in[3];
    const float* Wxfb = (const float*)d_in[4];
    const float* Whfw = (const float*)d_in[5];
    const float* Wxbw = (const float*)d_in[6];
    const float* Wxbb = (const float*)d_in[7];
    const float* Whbw = (const float*)d_in[8];
    float* out = (float*)d_out;

    dim3 g1(4, 256, 2);
    xproj_gemm<<<g1, 256>>>(x, Wxfw, Wxfb, Wxbw, Wxbb);

    rnn_rec<<<128, 256>>>(h0f, h0b, Whfw, Whbw, out);
}